// round 2
// baseline (speedup 1.0000x reference)
#include <cuda_runtime.h>
#include <cuda_bf16.h>

typedef unsigned long long ull;

// ---------------- scratch (no allocations allowed) ----------------
__device__ float2 g_K2[64 * 32];   // K[i][r] duplicated into both f32 halves
__device__ float2 g_c2[64];        // c[i] duplicated
__device__ float  g_T1[64 * 64];   // F @ P intermediate

__device__ __forceinline__ ull fma2(ull a, ull b, ull c) {
    ull d;
    asm("fma.rn.f32x2 %0, %1, %2, %3;" : "=l"(d) : "l"(a), "l"(b), "l"(c));
    return d;
}

// =================================================================
// Prep kernel: one block, 1024 threads. Computes
//   x_pred = F x
//   P_pred = F P F^T + Q
//   S      = P_pred[:32,:32] + R          (H = eye(32,64))
//   K^T    = GaussJordan([S | P_pred[:, :32]^T])
//   c      = x_pred - K x_pred[:32]
// =================================================================
__global__ void akf_prep(const float* __restrict__ F,
                         const float* __restrict__ Q,
                         const float* __restrict__ R,
                         const float* __restrict__ P,
                         const float* __restrict__ x) {
    __shared__ float sFT[64 * 68];   // sFT[k*68 + j] = F[j][k]  (pad 68 for 16B-aligned float4)
    __shared__ float sPP[64 * 64];
    __shared__ float sA[32][100];    // augmented [S | M^T], padded
    __shared__ float sxp[64];
    __shared__ float srinv[32];

    const int t = threadIdx.x;

    // stage F^T
    for (int e = t; e < 4096; e += 1024) {
        int i = e >> 6, k = e & 63;
        sFT[k * 68 + i] = F[e];
    }
    // x_pred
    if (t < 64) {
        float s = 0.f;
        #pragma unroll 8
        for (int k = 0; k < 64; k++) s += F[t * 64 + k] * x[k];
        sxp[t] = s;
    }
    __syncthreads();

    // T1 = F @ P   (thread -> 4 consecutive columns)
    {
        int i = t >> 4, j0 = (t & 15) * 4;
        float4 a = make_float4(0.f, 0.f, 0.f, 0.f);
        for (int k = 0; k < 64; k++) {
            float fv = sFT[k * 68 + i];
            float4 pv = *(const float4*)(P + k * 64 + j0);
            a.x += fv * pv.x; a.y += fv * pv.y; a.z += fv * pv.z; a.w += fv * pv.w;
        }
        *(float4*)(g_T1 + i * 64 + j0) = a;
    }
    __syncthreads();

    // PP = T1 @ F^T + Q
    {
        int i = t >> 4, j0 = (t & 15) * 4;
        float4 a = *(const float4*)(Q + i * 64 + j0);
        for (int k = 0; k < 64; k++) {
            float tv = g_T1[i * 64 + k];
            float4 fv = *(const float4*)(sFT + k * 68 + j0);
            a.x += tv * fv.x; a.y += tv * fv.y; a.z += tv * fv.z; a.w += tv * fv.w;
        }
        *(float4*)(sPP + i * 64 + j0) = a;
    }
    __syncthreads();

    // Build augmented system [S | M^T]  (S = PP[:32,:32] + R, M^T[r][i] = PP[i][r])
    for (int e = t; e < 32 * 96; e += 1024) {
        int r = e / 96, cc = e % 96;
        float v;
        if (cc < 32) v = sPP[r * 64 + cc] + R[r * 32 + cc];
        else         v = sPP[(cc - 32) * 64 + r];
        sA[r][cc] = v;
    }
    __syncthreads();

    // Gauss-Jordan, warp r owns row r (no pivoting: S ~ 2I, diag dominant)
    const int warp = t >> 5, lane = t & 31;
    for (int p = 0; p < 32; p++) {
        float pivinv = 1.0f / sA[p][p];
        float f = sA[warp][p] * pivinv;
        float a0 = sA[p][lane], a1 = sA[p][lane + 32], a2 = sA[p][lane + 64];
        __syncwarp();
        if (warp != p) {
            sA[warp][lane]      -= f * a0;
            sA[warp][lane + 32] -= f * a1;
            sA[warp][lane + 64] -= f * a2;
        }
        __syncthreads();
    }
    if (t < 32) srinv[t] = 1.0f / sA[t][t];
    __syncthreads();

    // K[i][r] = sA[r][32+i] / sA[r][r], duplicated to f32x2
    for (int e = t; e < 2048; e += 1024) {
        int i = e >> 5, r = e & 31;
        float v = sA[r][32 + i] * srinv[r];
        g_K2[e] = make_float2(v, v);
    }
    // c = x_pred - K x_pred[:32]
    if (t < 64) {
        float c = sxp[t];
        #pragma unroll
        for (int r = 0; r < 32; r++) c -= sA[r][32 + t] * srinv[r] * sxp[r];
        g_c2[t] = make_float2(c, c);
    }
}

// =================================================================
// Main kernel: out[i][j] = c[i] + sum_k K[i][k] * z[k][j]
// Block = 256 thr (8 warps). Warp w -> rows 8w..8w+7.
// Lane -> columns {j0+4*lane..+3} and {j0+128+4*lane..+3} (coalesced 128B).
// Tile = 256 columns / block-iteration. Packed f32x2 math.
// =================================================================
#define TJ 256

union V16 { ulonglong2 u; float4 f; };

__global__ void __launch_bounds__(256, 2)
akf_main(const float* __restrict__ z, float* __restrict__ out,
         int N, int ntiles) {
    __shared__ ull sK[64 * 32];
    __shared__ ull sc[64];

    for (int e = threadIdx.x; e < 2048; e += 256) sK[e] = ((const ull*)g_K2)[e];
    if (threadIdx.x < 64) sc[threadIdx.x] = ((const ull*)g_c2)[threadIdx.x];
    __syncthreads();

    const int warp = threadIdx.x >> 5, lane = threadIdx.x & 31;
    const int rowb = warp * 8;

    for (int tile = blockIdx.x; tile < ntiles; tile += gridDim.x) {
        const size_t j0 = (size_t)tile * TJ + lane * 4;
        const size_t j1 = j0 + 128;

        ull acc[8][4];
        #pragma unroll
        for (int i = 0; i < 8; i++) {
            ull cv = sc[rowb + i];
            acc[i][0] = cv; acc[i][1] = cv; acc[i][2] = cv; acc[i][3] = cv;
        }

        #pragma unroll 8
        for (int k = 0; k < 32; k++) {
            ulonglong2 za = *(const ulonglong2*)(z + (size_t)k * N + j0);
            ulonglong2 zb = *(const ulonglong2*)(z + (size_t)k * N + j1);
            #pragma unroll
            for (int i = 0; i < 8; i++) {
                ull kk = sK[(rowb + i) * 32 + k];
                acc[i][0] = fma2(kk, za.x, acc[i][0]);
                acc[i][1] = fma2(kk, za.y, acc[i][1]);
                acc[i][2] = fma2(kk, zb.x, acc[i][2]);
                acc[i][3] = fma2(kk, zb.y, acc[i][3]);
            }
        }

        #pragma unroll
        for (int i = 0; i < 8; i++) {
            V16 v0, v1;
            v0.u = make_ulonglong2(acc[i][0], acc[i][1]);
            v1.u = make_ulonglong2(acc[i][2], acc[i][3]);
            float* p = out + (size_t)(rowb + i) * N;
            __stcs((float4*)(p + j0), v0.f);
            __stcs((float4*)(p + j1), v1.f);
        }
    }
}

// scalar tail (only used if N % 256 != 0; N = 2^20 here so normally unused)
__global__ void akf_tail(const float* __restrict__ z, float* __restrict__ out,
                         int N, int start) {
    int j = start + blockIdx.x * blockDim.x + threadIdx.x;
    if (j >= N) return;
    float zv[32];
    #pragma unroll
    for (int r = 0; r < 32; r++) zv[r] = z[(size_t)r * N + j];
    for (int i = 0; i < 64; i++) {
        float s = g_c2[i].x;
        #pragma unroll
        for (int r = 0; r < 32; r++) s += g_K2[i * 32 + r].x * zv[r];
        out[(size_t)i * N + j] = s;
    }
}

extern "C" void kernel_launch(void* const* d_in, const int* in_sizes, int n_in,
                              void* d_out, int out_size) {
    const float* z = (const float*)d_in[0];
    const float* F = (const float*)d_in[1];
    // d_in[2] = H (identity eye(32,64) per problem spec; exploited analytically)
    const float* Q = (const float*)d_in[3];
    const float* R = (const float*)d_in[4];
    const float* P = (const float*)d_in[5];
    const float* x = (const float*)d_in[6];
    float* out = (float*)d_out;

    const int N = in_sizes[0] / 32;
    const int ntiles = N / TJ;

    akf_prep<<<1, 1024>>>(F, Q, R, P, x);

    if (ntiles > 0) {
        int grid = ntiles < 592 ? ntiles : 592;
        akf_main<<<grid, 256>>>(z, out, N, ntiles);
    }
    const int rem = N - ntiles * TJ;
    if (rem > 0) {
        akf_tail<<<(rem + 127) / 128, 128>>>(z, out, N, ntiles * TJ);
    }
}

// round 8
// speedup vs baseline: 1.0556x; 1.0556x over previous
#include <cuda_runtime.h>
#include <cuda_bf16.h>

typedef unsigned long long ull;

// ---------------- scratch (no allocations allowed) ----------------
__device__ float2 g_K2t[32 * 64];  // [r][i]: K[i][r] duplicated into both f32 halves
__device__ float2 g_c2[64];        // c[i] duplicated
__device__ float  g_T1[64 * 64];   // F @ P intermediate

__device__ __forceinline__ ull fma2(ull a, ull b, ull c) {
    ull d;
    asm("fma.rn.f32x2 %0, %1, %2, %3;" : "=l"(d) : "l"(a), "l"(b), "l"(c));
    return d;
}

union V16 { ulonglong2 u; float4 f; };

// =================================================================
// Prep kernel: one block, 1024 threads. Computes
//   x_pred = F x
//   P_pred = F P F^T + Q
//   S      = P_pred[:32,:32] + R          (H = eye(32,64))
//   K^T    = GaussJordan([S | P_pred[:, :32]^T])
//   c      = x_pred - K x_pred[:32]
// =================================================================
__global__ void akf_prep(const float* __restrict__ F,
                         const float* __restrict__ Q,
                         const float* __restrict__ R,
                         const float* __restrict__ P,
                         const float* __restrict__ x) {
    __shared__ float sFT[64 * 68];   // sFT[k*68 + j] = F[j][k]
    __shared__ float sPP[64 * 64];
    __shared__ float sA[32][100];    // augmented [S | M^T], padded
    __shared__ float sxp[64];
    __shared__ float srinv[32];

    const int t = threadIdx.x;

    // stage F^T
    for (int e = t; e < 4096; e += 1024) {
        int i = e >> 6, k = e & 63;
        sFT[k * 68 + i] = F[e];
    }
    // x_pred
    if (t < 64) {
        float s = 0.f;
        #pragma unroll 8
        for (int k = 0; k < 64; k++) s += F[t * 64 + k] * x[k];
        sxp[t] = s;
    }
    __syncthreads();

    // T1 = F @ P   (thread -> 4 consecutive columns)
    {
        int i = t >> 4, j0 = (t & 15) * 4;
        float4 a = make_float4(0.f, 0.f, 0.f, 0.f);
        for (int k = 0; k < 64; k++) {
            float fv = sFT[k * 68 + i];
            float4 pv = *(const float4*)(P + k * 64 + j0);
            a.x += fv * pv.x; a.y += fv * pv.y; a.z += fv * pv.z; a.w += fv * pv.w;
        }
        *(float4*)(g_T1 + i * 64 + j0) = a;
    }
    __syncthreads();

    // PP = T1 @ F^T + Q
    {
        int i = t >> 4, j0 = (t & 15) * 4;
        float4 a = *(const float4*)(Q + i * 64 + j0);
        for (int k = 0; k < 64; k++) {
            float tv = g_T1[i * 64 + k];
            float4 fv = *(const float4*)(sFT + k * 68 + j0);
            a.x += tv * fv.x; a.y += tv * fv.y; a.z += tv * fv.z; a.w += tv * fv.w;
        }
        *(float4*)(sPP + i * 64 + j0) = a;
    }
    __syncthreads();

    // Build augmented system [S | M^T]
    for (int e = t; e < 32 * 96; e += 1024) {
        int r = e / 96, cc = e % 96;
        float v;
        if (cc < 32) v = sPP[r * 64 + cc] + R[r * 32 + cc];
        else         v = sPP[(cc - 32) * 64 + r];
        sA[r][cc] = v;
    }
    __syncthreads();

    // Gauss-Jordan, warp r owns row r (S ~ 2I, diag dominant, no pivoting)
    const int warp = t >> 5, lane = t & 31;
    for (int p = 0; p < 32; p++) {
        float pivinv = 1.0f / sA[p][p];
        float f = sA[warp][p] * pivinv;
        float a0 = sA[p][lane], a1 = sA[p][lane + 32], a2 = sA[p][lane + 64];
        __syncwarp();
        if (warp != p) {
            sA[warp][lane]      -= f * a0;
            sA[warp][lane + 32] -= f * a1;
            sA[warp][lane + 64] -= f * a2;
        }
        __syncthreads();
    }
    if (t < 32) srinv[t] = 1.0f / sA[t][t];
    __syncthreads();

    // K[i][r] = sA[r][32+i] / sA[r][r], stored transposed [r][i], dup f32x2
    for (int e = t; e < 2048; e += 1024) {
        int r = e >> 6, i = e & 63;
        float v = sA[r][32 + i] * srinv[r];
        g_K2t[e] = make_float2(v, v);
    }
    // c = x_pred - K x_pred[:32]
    if (t < 64) {
        float c = sxp[t];
        #pragma unroll
        for (int r = 0; r < 32; r++) c -= sA[r][32 + t] * srinv[r] * sxp[r];
        g_c2[t] = make_float2(c, c);
    }
}

// =================================================================
// Main kernel: out[i][j] = c[i] + sum_k K[i][k] * z[k][j]
// Block = 512 thr (16 warps). Warp w -> rows 4w..4w+3 (all 64 rows/block,
// so each z column tile is loaded exactly ONCE per block -> once from DRAM).
// Lane -> cols {j0..j0+3} and {j0+128..+131}; tile = 256 cols/block.
// acc[4][4] = 32 regs -> 64-reg cap -> 2 CTAs/SM -> 32 warps (50% occ).
// Per k: 2x LDG.128 (z, streaming) + 2x LDS.128 (K broadcast) + 16 FFMA2.
// =================================================================
#define TJ 256

__global__ void __launch_bounds__(512, 2)
akf_main(const float* __restrict__ z, float* __restrict__ out, int N) {
    __shared__ ull sK[32 * 64];   // [k][row]
    __shared__ ull sc[64];

    const int tid = threadIdx.x;
    for (int e = tid; e < 2048; e += 512) sK[e] = ((const ull*)g_K2t)[e];
    if (tid < 64) sc[tid] = ((const ull*)g_c2)[tid];
    __syncthreads();

    const int warp = tid >> 5, lane = tid & 31;
    const int r0 = warp * 4;
    const size_t j0 = (size_t)blockIdx.x * TJ + lane * 4;

    ull acc[4][4];
    #pragma unroll
    for (int i = 0; i < 4; i++) {
        ull cv = sc[r0 + i];
        acc[i][0] = cv; acc[i][1] = cv; acc[i][2] = cv; acc[i][3] = cv;
    }

    const float* zp = z + j0;
    #pragma unroll 4
    for (int k = 0; k < 32; k++) {
        V16 za, zb;
        za.f = __ldcs((const float4*)(zp + (size_t)k * N));
        zb.f = __ldcs((const float4*)(zp + (size_t)k * N + 128));
        ulonglong2 kab = *(const ulonglong2*)(sK + k * 64 + r0);
        ulonglong2 kcd = *(const ulonglong2*)(sK + k * 64 + r0 + 2);

        acc[0][0] = fma2(kab.x, za.u.x, acc[0][0]);
        acc[0][1] = fma2(kab.x, za.u.y, acc[0][1]);
        acc[0][2] = fma2(kab.x, zb.u.x, acc[0][2]);
        acc[0][3] = fma2(kab.x, zb.u.y, acc[0][3]);

        acc[1][0] = fma2(kab.y, za.u.x, acc[1][0]);
        acc[1][1] = fma2(kab.y, za.u.y, acc[1][1]);
        acc[1][2] = fma2(kab.y, zb.u.x, acc[1][2]);
        acc[1][3] = fma2(kab.y, zb.u.y, acc[1][3]);

        acc[2][0] = fma2(kcd.x, za.u.x, acc[2][0]);
        acc[2][1] = fma2(kcd.x, za.u.y, acc[2][1]);
        acc[2][2] = fma2(kcd.x, zb.u.x, acc[2][2]);
        acc[2][3] = fma2(kcd.x, zb.u.y, acc[2][3]);

        acc[3][0] = fma2(kcd.y, za.u.x, acc[3][0]);
        acc[3][1] = fma2(kcd.y, za.u.y, acc[3][1]);
        acc[3][2] = fma2(kcd.y, zb.u.x, acc[3][2]);
        acc[3][3] = fma2(kcd.y, zb.u.y, acc[3][3]);
    }

    #pragma unroll
    for (int i = 0; i < 4; i++) {
        V16 v0, v1;
        v0.u = make_ulonglong2(acc[i][0], acc[i][1]);
        v1.u = make_ulonglong2(acc[i][2], acc[i][3]);
        float* p = out + (size_t)(r0 + i) * N;
        __stcs((float4*)(p + j0), v0.f);
        __stcs((float4*)(p + j0 + 128), v1.f);
    }
}

// scalar tail (covers remainder columns, or everything if N misaligned)
__global__ void akf_tail(const float* __restrict__ z, float* __restrict__ out,
                         int N, int start) {
    int j = start + blockIdx.x * blockDim.x + threadIdx.x;
    if (j >= N) return;
    float zv[32];
    #pragma unroll
    for (int r = 0; r < 32; r++) zv[r] = z[(size_t)r * N + j];
    for (int i = 0; i < 64; i++) {
        float s = g_c2[i].x;
        #pragma unroll
        for (int r = 0; r < 32; r++) s += g_K2t[r * 64 + i].x * zv[r];
        out[(size_t)i * N + j] = s;
    }
}

extern "C" void kernel_launch(void* const* d_in, const int* in_sizes, int n_in,
                              void* d_out, int out_size) {
    const float* z = (const float*)d_in[0];
    const float* F = (const float*)d_in[1];
    // d_in[2] = H (identity eye(32,64) per problem spec; exploited analytically)
    const float* Q = (const float*)d_in[3];
    const float* R = (const float*)d_in[4];
    const float* P = (const float*)d_in[5];
    const float* x = (const float*)d_in[6];
    float* out = (float*)d_out;

    const int N = in_sizes[0] / 32;

    akf_prep<<<1, 1024>>>(F, Q, R, P, x);

    int ntiles = (N % 4 == 0) ? (N / TJ) : 0;   // main needs 16B-aligned row stride
    if (ntiles > 0) {
        akf_main<<<ntiles, 512>>>(z, out, N);
    }
    const int rem = N - ntiles * TJ;
    if (rem > 0) {
        akf_tail<<<(rem + 127) / 128, 128>>>(z, out, N, ntiles * TJ);
    }
}

// round 13
// speedup vs baseline: 1.5688x; 1.4862x over previous
#include <cuda_runtime.h>
#include <cuda_bf16.h>
#include <cstdint>

typedef unsigned long long ull;
typedef unsigned int u32;

// ---------------- scratch (no allocations allowed) ----------------
__device__ float2 g_K2t[32 * 64];  // [k][row]: K[row][k] duplicated into both f32 halves
__device__ float2 g_c2[64];        // c[i] duplicated
__device__ float  g_T1[64 * 64];   // F @ P intermediate

__device__ __forceinline__ ull fma2(ull a, ull b, ull c) {
    ull d;
    asm("fma.rn.f32x2 %0, %1, %2, %3;" : "=l"(d) : "l"(a), "l"(b), "l"(c));
    return d;
}

__device__ __forceinline__ void cp16(u32 saddr, const float* g) {
    asm volatile("cp.async.cg.shared.global [%0], [%1], 16;" :: "r"(saddr), "l"(g));
}

union V16 { ulonglong2 u; float4 f; };

// =================================================================
// Prep kernel (unchanged): one block, 1024 threads.
//   x_pred = F x ; P_pred = F P F^T + Q ; S = P_pred[:32,:32] + R
//   K^T via Gauss-Jordan ; c = x_pred - K x_pred[:32]
// =================================================================
__global__ void akf_prep(const float* __restrict__ F,
                         const float* __restrict__ Q,
                         const float* __restrict__ R,
                         const float* __restrict__ P,
                         const float* __restrict__ x) {
    __shared__ float sFT[64 * 68];
    __shared__ float sPP[64 * 64];
    __shared__ float sA[32][100];
    __shared__ float sxp[64];
    __shared__ float srinv[32];

    const int t = threadIdx.x;

    for (int e = t; e < 4096; e += 1024) {
        int i = e >> 6, k = e & 63;
        sFT[k * 68 + i] = F[e];
    }
    if (t < 64) {
        float s = 0.f;
        #pragma unroll 8
        for (int k = 0; k < 64; k++) s += F[t * 64 + k] * x[k];
        sxp[t] = s;
    }
    __syncthreads();

    {
        int i = t >> 4, j0 = (t & 15) * 4;
        float4 a = make_float4(0.f, 0.f, 0.f, 0.f);
        for (int k = 0; k < 64; k++) {
            float fv = sFT[k * 68 + i];
            float4 pv = *(const float4*)(P + k * 64 + j0);
            a.x += fv * pv.x; a.y += fv * pv.y; a.z += fv * pv.z; a.w += fv * pv.w;
        }
        *(float4*)(g_T1 + i * 64 + j0) = a;
    }
    __syncthreads();

    {
        int i = t >> 4, j0 = (t & 15) * 4;
        float4 a = *(const float4*)(Q + i * 64 + j0);
        for (int k = 0; k < 64; k++) {
            float tv = g_T1[i * 64 + k];
            float4 fv = *(const float4*)(sFT + k * 68 + j0);
            a.x += tv * fv.x; a.y += tv * fv.y; a.z += tv * fv.z; a.w += tv * fv.w;
        }
        *(float4*)(sPP + i * 64 + j0) = a;
    }
    __syncthreads();

    for (int e = t; e < 32 * 96; e += 1024) {
        int r = e / 96, cc = e % 96;
        float v;
        if (cc < 32) v = sPP[r * 64 + cc] + R[r * 32 + cc];
        else         v = sPP[(cc - 32) * 64 + r];
        sA[r][cc] = v;
    }
    __syncthreads();

    const int warp = t >> 5, lane = t & 31;
    for (int p = 0; p < 32; p++) {
        float pivinv = 1.0f / sA[p][p];
        float f = sA[warp][p] * pivinv;
        float a0 = sA[p][lane], a1 = sA[p][lane + 32], a2 = sA[p][lane + 64];
        __syncwarp();
        if (warp != p) {
            sA[warp][lane]      -= f * a0;
            sA[warp][lane + 32] -= f * a1;
            sA[warp][lane + 64] -= f * a2;
        }
        __syncthreads();
    }
    if (t < 32) srinv[t] = 1.0f / sA[t][t];
    __syncthreads();

    for (int e = t; e < 2048; e += 1024) {
        int r = e >> 6, i = e & 63;
        float v = sA[r][32 + i] * srinv[r];
        g_K2t[e] = make_float2(v, v);
    }
    if (t < 64) {
        float c = sxp[t];
        #pragma unroll
        for (int r = 0; r < 32; r++) c -= sA[r][32 + t] * srinv[r] * sxp[r];
        g_c2[t] = make_float2(c, c);
    }
}

// =================================================================
// Main kernel: out[i][j] = c[i] + sum_k K[i][k] * z[k][j]
// 256 thr (8 warps), 4 CTAs/SM (64-reg cap, 32.5KB smem). Warp w ->
// rows 8w..8w+7; lane -> 4 cols. Tile = 128 cols; z staged to smem in
// two 16-k halves via cp.async (register-free MLP -> DRAM saturation).
// Inner loop: all-immediate smem addressing, 16 FFMA2 + 5 LDS per warp-k.
// =================================================================
#define TJ 128

__global__ void __launch_bounds__(256, 4)
akf_main(const float* __restrict__ z, float* __restrict__ out,
         int N, int ntiles) {
    __shared__ ull   sK[32 * 64];        // [k][row] dup, 16KB
    __shared__ ull   sc[64];
    __shared__ float sz0[16 * TJ];       // stage 0: k-half rows, 8KB
    __shared__ float sz1[16 * TJ];       // stage 1

    const int tid = threadIdx.x;
    for (int e = tid; e < 2048; e += 256) sK[e] = ((const ull*)g_K2t)[e];
    if (tid < 64) sc[tid] = ((const ull*)g_c2)[tid];

    const int warp = tid >> 5, lane = tid & 31;
    const int r0 = warp * 8;

    // prefetch mapping: 16 rows x 512B per stage; 16 threads/row, 32B each
    const int kl = tid >> 4;            // local k row 0..15
    const int ch = tid & 15;            // 8-float column chunk
    const u32 sd0 = (u32)__cvta_generic_to_shared(&sz0[kl * TJ + ch * 8]);
    const u32 sd1 = (u32)__cvta_generic_to_shared(&sz1[kl * TJ + ch * 8]);
    const float* gbase = z + (size_t)kl * N + ch * 8;

    __syncthreads();                    // sK/sc ready

    const int grid = gridDim.x;
    int tile = blockIdx.x;
    if (tile >= ntiles) return;

    // prologue: prefetch (tile, half 0) into stage 0
    {
        const float* g = gbase + (size_t)tile * TJ;
        cp16(sd0, g); cp16(sd0 + 16, g + 4);
    }
    asm volatile("cp.async.commit_group;");

    for (; tile < ntiles; tile += grid) {
        ull acc[8][2];
        #pragma unroll
        for (int i = 0; i < 8; i++) {
            ull cv = sc[r0 + i];
            acc[i][0] = cv; acc[i][1] = cv;
        }

        // ---- half 0: prefetch (tile, half1) -> stage1, compute stage0 ----
        {
            const float* g = gbase + (size_t)16 * N + (size_t)tile * TJ;
            cp16(sd1, g); cp16(sd1 + 16, g + 4);
        }
        asm volatile("cp.async.commit_group;");
        asm volatile("cp.async.wait_group 1;");
        __syncthreads();

        #pragma unroll
        for (int k = 0; k < 16; k++) {
            V16 z4; z4.f = *(const float4*)&sz0[k * TJ + lane * 4];
            const ull* Kp = sK + k * 64 + r0;
            #pragma unroll
            for (int g = 0; g < 4; g++) {
                ulonglong2 kk = *(const ulonglong2*)(Kp + g * 2);
                acc[g*2+0][0] = fma2(kk.x, z4.u.x, acc[g*2+0][0]);
                acc[g*2+0][1] = fma2(kk.x, z4.u.y, acc[g*2+0][1]);
                acc[g*2+1][0] = fma2(kk.y, z4.u.x, acc[g*2+1][0]);
                acc[g*2+1][1] = fma2(kk.y, z4.u.y, acc[g*2+1][1]);
            }
        }
        __syncthreads();

        // ---- half 1: prefetch (tile+grid, half0) -> stage0, compute stage1 ----
        if (tile + grid < ntiles) {
            const float* g = gbase + (size_t)(tile + grid) * TJ;
            cp16(sd0, g); cp16(sd0 + 16, g + 4);
        }
        asm volatile("cp.async.commit_group;");
        asm volatile("cp.async.wait_group 1;");
        __syncthreads();

        #pragma unroll
        for (int k = 0; k < 16; k++) {
            V16 z4; z4.f = *(const float4*)&sz1[k * TJ + lane * 4];
            const ull* Kp = sK + (16 + k) * 64 + r0;
            #pragma unroll
            for (int g = 0; g < 4; g++) {
                ulonglong2 kk = *(const ulonglong2*)(Kp + g * 2);
                acc[g*2+0][0] = fma2(kk.x, z4.u.x, acc[g*2+0][0]);
                acc[g*2+0][1] = fma2(kk.x, z4.u.y, acc[g*2+0][1]);
                acc[g*2+1][0] = fma2(kk.y, z4.u.x, acc[g*2+1][0]);
                acc[g*2+1][1] = fma2(kk.y, z4.u.y, acc[g*2+1][1]);
            }
        }
        __syncthreads();

        // store 8 rows x 4 cols
        const size_t j0 = (size_t)tile * TJ + lane * 4;
        #pragma unroll
        for (int i = 0; i < 8; i++) {
            V16 v; v.u = make_ulonglong2(acc[i][0], acc[i][1]);
            __stcs((float4*)(out + (size_t)(r0 + i) * N + j0), v.f);
        }
    }
}

// scalar tail (remainder columns, or everything if N misaligned)
__global__ void akf_tail(const float* __restrict__ z, float* __restrict__ out,
                         int N, int start) {
    int j = start + blockIdx.x * blockDim.x + threadIdx.x;
    if (j >= N) return;
    float zv[32];
    #pragma unroll
    for (int r = 0; r < 32; r++) zv[r] = z[(size_t)r * N + j];
    for (int i = 0; i < 64; i++) {
        float s = g_c2[i].x;
        #pragma unroll
        for (int r = 0; r < 32; r++) s += g_K2t[r * 64 + i].x * zv[r];
        out[(size_t)i * N + j] = s;
    }
}

extern "C" void kernel_launch(void* const* d_in, const int* in_sizes, int n_in,
                              void* d_out, int out_size) {
    const float* z = (const float*)d_in[0];
    const float* F = (const float*)d_in[1];
    // d_in[2] = H (identity eye(32,64) per problem spec; exploited analytically)
    const float* Q = (const float*)d_in[3];
    const float* R = (const float*)d_in[4];
    const float* P = (const float*)d_in[5];
    const float* x = (const float*)d_in[6];
    float* out = (float*)d_out;

    const int N = in_sizes[0] / 32;

    akf_prep<<<1, 1024>>>(F, Q, R, P, x);

    int ntiles = (N % 4 == 0) ? (N / TJ) : 0;   // main needs 16B-aligned rows
    if (ntiles > 0) {
        int grid = ntiles < 592 ? ntiles : 592;  // 4 CTAs x 148 SMs
        akf_main<<<grid, 256>>>(z, out, N, ntiles);
    }
    const int rem = N - ntiles * TJ;
    if (rem > 0) {
        akf_tail<<<(rem + 127) / 128, 128>>>(z, out, N, ntiles * TJ);
    }
}

// round 14
// speedup vs baseline: 1.6522x; 1.0531x over previous
#include <cuda_runtime.h>
#include <cuda_bf16.h>
#include <cstdint>

typedef unsigned long long ull;
typedef unsigned int u32;

// ---------------- scratch (no allocations allowed) ----------------
__device__ float2 g_K2t[32 * 64];  // [k][row]: K[row][k] duplicated into both f32 halves
__device__ float2 g_c2[64];        // c[i] duplicated
__device__ float  g_T1[64 * 64];   // F @ P intermediate

__device__ __forceinline__ ull fma2(ull a, ull b, ull c) {
    ull d;
    asm("fma.rn.f32x2 %0, %1, %2, %3;" : "=l"(d) : "l"(a), "l"(b), "l"(c));
    return d;
}

__device__ __forceinline__ void cp16(u32 saddr, const float* g) {
    asm volatile("cp.async.cg.shared.global [%0], [%1], 16;" :: "r"(saddr), "l"(g));
}

union V16 { ulonglong2 u; float4 f; };

// =================================================================
// Prep kernel (unchanged): one block, 1024 threads.
//   x_pred = F x ; P_pred = F P F^T + Q ; S = P_pred[:32,:32] + R
//   K^T via Gauss-Jordan ; c = x_pred - K x_pred[:32]
// =================================================================
__global__ void akf_prep(const float* __restrict__ F,
                         const float* __restrict__ Q,
                         const float* __restrict__ R,
                         const float* __restrict__ P,
                         const float* __restrict__ x) {
    __shared__ float sFT[64 * 68];
    __shared__ float sPP[64 * 64];
    __shared__ float sA[32][100];
    __shared__ float sxp[64];
    __shared__ float srinv[32];

    const int t = threadIdx.x;

    for (int e = t; e < 4096; e += 1024) {
        int i = e >> 6, k = e & 63;
        sFT[k * 68 + i] = F[e];
    }
    if (t < 64) {
        float s = 0.f;
        #pragma unroll 8
        for (int k = 0; k < 64; k++) s += F[t * 64 + k] * x[k];
        sxp[t] = s;
    }
    __syncthreads();

    {
        int i = t >> 4, j0 = (t & 15) * 4;
        float4 a = make_float4(0.f, 0.f, 0.f, 0.f);
        for (int k = 0; k < 64; k++) {
            float fv = sFT[k * 68 + i];
            float4 pv = *(const float4*)(P + k * 64 + j0);
            a.x += fv * pv.x; a.y += fv * pv.y; a.z += fv * pv.z; a.w += fv * pv.w;
        }
        *(float4*)(g_T1 + i * 64 + j0) = a;
    }
    __syncthreads();

    {
        int i = t >> 4, j0 = (t & 15) * 4;
        float4 a = *(const float4*)(Q + i * 64 + j0);
        for (int k = 0; k < 64; k++) {
            float tv = g_T1[i * 64 + k];
            float4 fv = *(const float4*)(sFT + k * 68 + j0);
            a.x += tv * fv.x; a.y += tv * fv.y; a.z += tv * fv.z; a.w += tv * fv.w;
        }
        *(float4*)(sPP + i * 64 + j0) = a;
    }
    __syncthreads();

    for (int e = t; e < 32 * 96; e += 1024) {
        int r = e / 96, cc = e % 96;
        float v;
        if (cc < 32) v = sPP[r * 64 + cc] + R[r * 32 + cc];
        else         v = sPP[(cc - 32) * 64 + r];
        sA[r][cc] = v;
    }
    __syncthreads();

    const int warp = t >> 5, lane = t & 31;
    for (int p = 0; p < 32; p++) {
        float pivinv = 1.0f / sA[p][p];
        float f = sA[warp][p] * pivinv;
        float a0 = sA[p][lane], a1 = sA[p][lane + 32], a2 = sA[p][lane + 64];
        __syncwarp();
        if (warp != p) {
            sA[warp][lane]      -= f * a0;
            sA[warp][lane + 32] -= f * a1;
            sA[warp][lane + 64] -= f * a2;
        }
        __syncthreads();
    }
    if (t < 32) srinv[t] = 1.0f / sA[t][t];
    __syncthreads();

    for (int e = t; e < 2048; e += 1024) {
        int r = e >> 6, i = e & 63;
        float v = sA[r][32 + i] * srinv[r];
        g_K2t[e] = make_float2(v, v);
    }
    if (t < 64) {
        float c = sxp[t];
        #pragma unroll
        for (int r = 0; r < 32; r++) c -= sA[r][32 + t] * srinv[r] * sxp[r];
        g_c2[t] = make_float2(c, c);
    }
}

// =================================================================
// Main kernel: out[i][j] = c[i] + sum_k K[i][k] * z[k][j]
// 256 thr (8 warps), 4 CTAs/SM. Warp w -> rows 8w..8w+7; lane -> 4 cols.
// Tile = 128 cols; k split into two 16-row halves. TRIPLE-buffered
// cp.async staging (prefetch distance 2 -> two 8KB groups in flight
// during every compute phase), exactly ONE __syncthreads per half.
// Inner loop: immediate smem addressing, 16 FFMA2 + 5 LDS per warp-k.
// =================================================================
#define TJ 128

__global__ void __launch_bounds__(256, 4)
akf_main(const float* __restrict__ z, float* __restrict__ out,
         int N, int ntiles) {
    __shared__ ull   sK[32 * 64];          // [k][row] dup, 16KB
    __shared__ ull   sc[64];
    __shared__ float sz[3][16 * TJ];       // 3 stages x 8KB

    const int tid = threadIdx.x;
    for (int e = tid; e < 2048; e += 256) sK[e] = ((const ull*)g_K2t)[e];
    if (tid < 64) sc[tid] = ((const ull*)g_c2)[tid];

    const int warp = tid >> 5, lane = tid & 31;
    const int r0 = warp * 8;

    // prefetch mapping: stage = 16 k-rows x 512B; thread -> 32B (2x cp16)
    const int kl = tid >> 4;               // k row within stage 0..15
    const int ch = tid & 15;               // 8-float chunk
    u32 sd[3];
    #pragma unroll
    for (int s = 0; s < 3; s++)
        sd[s] = (u32)__cvta_generic_to_shared(&sz[s][kl * TJ + ch * 8]);
    const float* gb0 = z + (size_t)kl * N + ch * 8;            // half 0 base
    const float* gb1 = gb0 + (size_t)16 * N;                   // half 1 base

    __syncthreads();                       // sK/sc ready

    const int grid = gridDim.x;
    int tile = blockIdx.x;
    if (tile >= ntiles) return;

    // prologue: prefetch (tile, h0)->slot0, (tile, h1)->slot1
    {
        const float* g0 = gb0 + (size_t)tile * TJ;
        cp16(sd[0], g0); cp16(sd[0] + 16, g0 + 4);
        asm volatile("cp.async.commit_group;");
        const float* g1 = gb1 + (size_t)tile * TJ;
        cp16(sd[1], g1); cp16(sd[1] + 16, g1 + 4);
        asm volatile("cp.async.commit_group;");
    }

    int slot = 0;
    for (; tile < ntiles; tile += grid) {
        const int nt = tile + grid;
        const bool more = nt < ntiles;

        ull acc[8][2];
        #pragma unroll
        for (int i = 0; i < 8; i++) {
            ull cv = sc[r0 + i];
            acc[i][0] = cv; acc[i][1] = cv;
        }

        // ================= half 0 =================
        asm volatile("cp.async.wait_group 1;");
        __syncthreads();
        {   // prefetch (next tile, h0) into slot+2
            int ps = slot + 2; if (ps >= 3) ps -= 3;
            if (more) {
                const float* g = gb0 + (size_t)nt * TJ;
                cp16(sd[ps], g); cp16(sd[ps] + 16, g + 4);
            }
            asm volatile("cp.async.commit_group;");
        }
        {
            const float* p = sz[slot];
            #pragma unroll
            for (int k = 0; k < 16; k++) {
                V16 z4; z4.f = *(const float4*)&p[k * TJ + lane * 4];
                const ull* Kp = sK + k * 64 + r0;
                #pragma unroll
                for (int g = 0; g < 4; g++) {
                    ulonglong2 kk = *(const ulonglong2*)(Kp + g * 2);
                    acc[g*2+0][0] = fma2(kk.x, z4.u.x, acc[g*2+0][0]);
                    acc[g*2+0][1] = fma2(kk.x, z4.u.y, acc[g*2+0][1]);
                    acc[g*2+1][0] = fma2(kk.y, z4.u.x, acc[g*2+1][0]);
                    acc[g*2+1][1] = fma2(kk.y, z4.u.y, acc[g*2+1][1]);
                }
            }
        }
        slot = (slot + 1 < 3) ? slot + 1 : 0;

        // ================= half 1 =================
        asm volatile("cp.async.wait_group 1;");
        __syncthreads();
        {   // prefetch (next tile, h1) into slot+2
            int ps = slot + 2; if (ps >= 3) ps -= 3;
            if (more) {
                const float* g = gb1 + (size_t)nt * TJ;
                cp16(sd[ps], g); cp16(sd[ps] + 16, g + 4);
            }
            asm volatile("cp.async.commit_group;");
        }
        {
            const float* p = sz[slot];
            #pragma unroll
            for (int k = 0; k < 16; k++) {
                V16 z4; z4.f = *(const float4*)&p[k * TJ + lane * 4];
                const ull* Kp = sK + (16 + k) * 64 + r0;
                #pragma unroll
                for (int g = 0; g < 4; g++) {
                    ulonglong2 kk = *(const ulonglong2*)(Kp + g * 2);
                    acc[g*2+0][0] = fma2(kk.x, z4.u.x, acc[g*2+0][0]);
                    acc[g*2+0][1] = fma2(kk.x, z4.u.y, acc[g*2+0][1]);
                    acc[g*2+1][0] = fma2(kk.y, z4.u.x, acc[g*2+1][0]);
                    acc[g*2+1][1] = fma2(kk.y, z4.u.y, acc[g*2+1][1]);
                }
            }
        }
        slot = (slot + 1 < 3) ? slot + 1 : 0;

        // store 8 rows x 4 cols (streaming)
        const size_t j0 = (size_t)tile * TJ + lane * 4;
        #pragma unroll
        for (int i = 0; i < 8; i++) {
            V16 v; v.u = make_ulonglong2(acc[i][0], acc[i][1]);
            __stcs((float4*)(out + (size_t)(r0 + i) * N + j0), v.f);
        }
    }
}

// scalar tail (remainder columns, or everything if N misaligned)
__global__ void akf_tail(const float* __restrict__ z, float* __restrict__ out,
                         int N, int start) {
    int j = start + blockIdx.x * blockDim.x + threadIdx.x;
    if (j >= N) return;
    float zv[32];
    #pragma unroll
    for (int r = 0; r < 32; r++) zv[r] = z[(size_t)r * N + j];
    for (int i = 0; i < 64; i++) {
        float s = g_c2[i].x;
        #pragma unroll
        for (int r = 0; r < 32; r++) s += g_K2t[r * 64 + i].x * zv[r];
        out[(size_t)i * N + j] = s;
    }
}

extern "C" void kernel_launch(void* const* d_in, const int* in_sizes, int n_in,
                              void* d_out, int out_size) {
    const float* z = (const float*)d_in[0];
    const float* F = (const float*)d_in[1];
    // d_in[2] = H (identity eye(32,64) per problem spec; exploited analytically)
    const float* Q = (const float*)d_in[3];
    const float* R = (const float*)d_in[4];
    const float* P = (const float*)d_in[5];
    const float* x = (const float*)d_in[6];
    float* out = (float*)d_out;

    const int N = in_sizes[0] / 32;

    akf_prep<<<1, 1024>>>(F, Q, R, P, x);

    int ntiles = (N % 4 == 0) ? (N / TJ) : 0;   // main needs 16B-aligned rows
    if (ntiles > 0) {
        int grid = ntiles < 592 ? ntiles : 592;  // 4 CTAs x 148 SMs
        akf_main<<<grid, 256>>>(z, out, N, ntiles);
    }
    const int rem = N - ntiles * TJ;
    if (rem > 0) {
        akf_tail<<<(rem + 127) / 128, 128>>>(z, out, N, ntiles * TJ);
    }
}